// round 16
// baseline (speedup 1.0000x reference)
#include <cuda_runtime.h>
#include <cuda_bf16.h>
#include <cstddef>

// SAPA R15: un-split fused attention (1px/thread, full C, softmax in-kernel,
// launch_bounds(256,3)) + R7 kproj + R13 agg. No tcgen05 (unsupported by build).
#define B_      4
#define C_      256
#define E_      32
#define NPIX_LO 4096
#define NPIX_HI 16384
#define KSTR    36
#define EPSF    1e-5f

typedef unsigned long long ull;

#define FMA2(d, a, b, c) \
    asm("fma.rn.f32x2 %0, %1, %2, %3;" : "=l"(d) : "l"(a), "l"(b), "l"(c))

__device__ __forceinline__ ull pack2(float lo, float hi) {
    ull r; asm("mov.b64 %0, {%1, %2};" : "=l"(r) : "f"(lo), "f"(hi)); return r;
}
__device__ __forceinline__ ull dup2(float v) { return pack2(v, v); }
__device__ __forceinline__ void unpack2(float& lo, float& hi, ull d) {
    asm("mov.b64 {%0, %1}, %2;" : "=f"(lo), "=f"(hi) : "l"(d));
}

// ---------------- device scratch ----------------
__device__ float  g_ps[640];
__device__ float  g_pss[640];
__device__ float2 g_st_y[B_ * C_];
__device__ float2 g_st_x[B_ * C_];
__device__ float  g_qwT[C_ * E_];              // [c][e]
__device__ float  g_kwT[C_ * E_];              // [c][e]
__device__ float  g_k[B_ * E_ * NPIX_LO];      // [b][e][pix_lo]
__device__ float  g_attn[B_ * 25 * NPIX_HI];   // [b][o][pix_hi]

// ============================================================
// Kernel 1: partial sums. blocks [0,512): y chunks; [512,640): x groups.
// ============================================================
__global__ void __launch_bounds__(256)
stats_partial_kernel(const float* __restrict__ y, const float* __restrict__ x)
{
    int bid = blockIdx.x, tid = threadIdx.x;
    const float4* p = (bid < 512)
        ? (const float4*)y + (size_t)bid * 8192
        : (const float4*)x + (size_t)(bid - 512) * 8192;

    float s = 0.f, ss = 0.f;
#pragma unroll 4
    for (int i = tid; i < 8192; i += 256) {
        float4 v = p[i];
        s  += (v.x + v.y) + (v.z + v.w);
        ss += (v.x*v.x + v.y*v.y) + (v.z*v.z + v.w*v.w);
    }
#pragma unroll
    for (int off = 16; off > 0; off >>= 1) {
        s  += __shfl_xor_sync(0xffffffffu, s,  off);
        ss += __shfl_xor_sync(0xffffffffu, ss, off);
    }
    __shared__ float ws[8], wss[8];
    if ((tid & 31) == 0) { ws[tid >> 5] = s; wss[tid >> 5] = ss; }
    __syncthreads();
    if (tid == 0) {
        float ts = 0.f, tss = 0.f;
#pragma unroll
        for (int w = 0; w < 8; w++) { ts += ws[w]; tss += wss[w]; }
        g_ps[bid] = ts; g_pss[bid] = tss;
    }
}

// ============================================================
// Kernel 2: finalize stats -> tables; transpose weights (R7).
// ============================================================
__global__ void __launch_bounds__(256)
finalize_kernel(const float* __restrict__ qw, const float* __restrict__ kw,
                const float* __restrict__ gyw, const float* __restrict__ gyb,
                const float* __restrict__ gxw, const float* __restrict__ gxb)
{
    int tid = threadIdx.x;
    if (blockIdx.x == 0) {
        __shared__ float mu_s[256], rs_s[256];
        {
            float s, ss, n;
            if (tid < 128) {
                s  = (g_ps[4*tid]  + g_ps[4*tid+1])  + (g_ps[4*tid+2]  + g_ps[4*tid+3]);
                ss = (g_pss[4*tid] + g_pss[4*tid+1]) + (g_pss[4*tid+2] + g_pss[4*tid+3]);
                n = 131072.f;
            } else {
                int g = tid - 128;
                s = g_ps[512 + g]; ss = g_pss[512 + g]; n = 32768.f;
            }
            float mu  = s / n;
            float var = ss / n - mu * mu;
            mu_s[tid] = mu; rs_s[tid] = rsqrtf(var + EPSF);
        }
        __syncthreads();
        for (int i = tid; i < 1024; i += 256) {
            int b = i >> 8, c = i & 255, g = c >> 3;
            {
                float mu = mu_s[b*32 + g], r = rs_s[b*32 + g];
                float sc = r * gyw[c];
                g_st_y[i] = make_float2(sc, gyb[c] - mu * sc);
            }
            {
                float mu = mu_s[128 + b*32 + g], r = rs_s[128 + b*32 + g];
                float sc = r * gxw[c];
                g_st_x[i] = make_float2(sc, gxb[c] - mu * sc);
            }
        }
    } else {
        int i = (blockIdx.x - 1) * 256 + tid;
        int c = i >> 5, e = i & 31;
        g_qwT[i] = qw[e * C_ + c];
        g_kwT[i] = kw[e * C_ + c];
    }
}

// ============================================================
// Kernel 3: k projection (R7 exact). grid (128, 4) x 256.
// ============================================================
__global__ void __launch_bounds__(256)
kproj_kernel(const float* __restrict__ x, const float* __restrict__ k_b)
{
    __shared__ float sm[8448 + 512];
    float* w_s = sm;
    float* r_s = sm;
    float* s_s = sm + 8448;
    float* t_s = sm + 8704;

    int tid = threadIdx.x;
    int b   = blockIdx.y;
    int p   = tid & 31;
    int pix = blockIdx.x * 32 + p;

    for (int i = tid; i < (C_ * E_) / 4; i += 256)
        ((float4*)w_s)[i] = ((const float4*)g_kwT)[i];
    {
        float2 st = g_st_x[b * C_ + tid];
        s_s[tid] = st.x; t_s[tid] = st.y;
    }
    __syncthreads();

    const float* xp = x + (size_t)b * C_ * NPIX_LO + pix;
    const ulonglong2* w2 = (const ulonglong2*)w_s;
    const float4* s4 = (const float4*)s_s;
    const float4* t4 = (const float4*)t_s;

    ull qa2[16];
#pragma unroll
    for (int j = 0; j < 16; j++) qa2[j] = 0ull;

    int cbase = (tid >> 5) * 32;
#pragma unroll 2
    for (int c0 = cbase; c0 < cbase + 32; c0 += 8) {
        float xv[8];
#pragma unroll
        for (int j = 0; j < 8; j++)
            xv[j] = xp[(size_t)(c0 + j) * NPIX_LO];
        float4 scA = s4[c0 >> 2], tcA = t4[c0 >> 2];
        float4 scB = s4[(c0 >> 2) + 1], tcB = t4[(c0 >> 2) + 1];
        ull u[8];
        u[0] = dup2(fmaf(xv[0], scA.x, tcA.x));
        u[1] = dup2(fmaf(xv[1], scA.y, tcA.y));
        u[2] = dup2(fmaf(xv[2], scA.z, tcA.z));
        u[3] = dup2(fmaf(xv[3], scA.w, tcA.w));
        u[4] = dup2(fmaf(xv[4], scB.x, tcB.x));
        u[5] = dup2(fmaf(xv[5], scB.y, tcB.y));
        u[6] = dup2(fmaf(xv[6], scB.z, tcB.z));
        u[7] = dup2(fmaf(xv[7], scB.w, tcB.w));
#pragma unroll
        for (int jj = 0; jj < 8; jj++) {
#pragma unroll
            for (int j = 0; j < 8; j++) {
                ulonglong2 wv = w2[(c0 + jj) * 8 + j];
                FMA2(qa2[2*j],   wv.x, u[jj], qa2[2*j]);
                FMA2(qa2[2*j+1], wv.y, u[jj], qa2[2*j+1]);
            }
        }
    }

    __syncthreads();
#pragma unroll
    for (int j = 0; j < 16; j++) {
        float lo, hi; unpack2(lo, hi, qa2[j]);
        r_s[tid * 33 + 2*j]     = lo;
        r_s[tid * 33 + 2*j + 1] = hi;
    }
    __syncthreads();

    int q4 = tid >> 5;
    int p2 = tid & 31;
    float acc[4];
#pragma unroll
    for (int j = 0; j < 4; j++) acc[j] = __ldg(&k_b[q4 * 4 + j]);
#pragma unroll
    for (int s = 0; s < 8; s++) {
        const float* rp = &r_s[(s * 32 + p2) * 33 + q4 * 4];
#pragma unroll
        for (int j = 0; j < 4; j++) acc[j] += rp[j];
    }
    int pix2 = blockIdx.x * 32 + p2;
#pragma unroll
    for (int j = 0; j < 4; j++)
        g_k[((size_t)(b * E_ + q4 * 4 + j) << 12) + pix2] = acc[j];
}

// ============================================================
// Kernel 4: fused q-proj + logits + softmax -> g_attn.
// grid (8, 8, 4) x 256; thread = 1 hi px of a 16x16 hi tile (8x8 lo).
// smem floats: w_s 256*36=9216 | sy 256 | ty 256 | k_s 144*36=5184
//   = 14912 floats = 59648 B  (3 blocks/SM = 175 KB)
// ============================================================
__global__ void __launch_bounds__(256, 3)
attn_kernel(const float* __restrict__ y, const float* __restrict__ q_b)
{
    extern __shared__ float smA[];
    float* w_s  = smA;             // [c][e] rows stride 36
    float* sy_s = smA + 9216;
    float* ty_s = smA + 9472;
    float* k_s  = smA + 9728;      // [pt][e] stride 36

    int tid = threadIdx.x;
    int b   = blockIdx.z;
    int th0 = blockIdx.y * 8;
    int tw0 = blockIdx.x * 8;

    for (int i = tid; i < 2048; i += 256) {          // 2048 float4 = 8192 floats
        float4 v = ((const float4*)g_qwT)[i];
        int c = i >> 3, k4 = i & 7;
        *(float4*)&w_s[c * KSTR + k4 * 4] = v;
    }
    {
        float2 st = g_st_y[b * C_ + tid];
        sy_s[tid] = st.x; ty_s[tid] = st.y;
    }
    for (int i = tid; i < E_ * 144; i += 256) {
        int e  = i / 144, pt = i - e * 144;
        int jy = pt / 12, jx = pt - jy * 12;
        int gy = th0 - 2 + jy, gx = tw0 - 2 + jx;
        float v = 0.f;
        if (gy >= 0 && gy < 64 && gx >= 0 && gx < 64)
            v = g_k[((size_t)(b * E_ + e) << 12) + (gy << 6) + gx];
        k_s[pt * KSTR + e] = v;
    }
    __syncthreads();

    int oy = tid >> 4, ox = tid & 15;
    int gy2 = th0 * 2 + oy, gx2 = tw0 * 2 + ox;
    int pixhi = (gy2 << 7) + gx2;
    const float* yp = y + (size_t)b * C_ * NPIX_HI + pixhi;
    const float4* sy4 = (const float4*)sy_s;
    const float4* ty4 = (const float4*)ty_s;

    ull qa[16];
#pragma unroll
    for (int j = 0; j < 16; j++)
        qa[j] = pack2(__ldg(&q_b[2*j]), __ldg(&q_b[2*j + 1]));

    for (int c0 = 0; c0 < C_; c0 += 8) {
        float yv[8];
#pragma unroll
        for (int j = 0; j < 8; j++)
            yv[j] = yp[(size_t)(c0 + j) * NPIX_HI];
        float4 scA = sy4[c0 >> 2], tcA = ty4[c0 >> 2];
        float4 scB = sy4[(c0 >> 2) + 1], tcB = ty4[(c0 >> 2) + 1];
        ull u[8];
        u[0] = dup2(fmaf(yv[0], scA.x, tcA.x));
        u[1] = dup2(fmaf(yv[1], scA.y, tcA.y));
        u[2] = dup2(fmaf(yv[2], scA.z, tcA.z));
        u[3] = dup2(fmaf(yv[3], scA.w, tcA.w));
        u[4] = dup2(fmaf(yv[4], scB.x, tcB.x));
        u[5] = dup2(fmaf(yv[5], scB.y, tcB.y));
        u[6] = dup2(fmaf(yv[6], scB.z, tcB.z));
        u[7] = dup2(fmaf(yv[7], scB.w, tcB.w));
#pragma unroll
        for (int jj = 0; jj < 8; jj++) {
            const ulonglong2* wv = (const ulonglong2*)&w_s[(c0 + jj) * KSTR];
#pragma unroll
            for (int j = 0; j < 8; j++) {
                ulonglong2 w = wv[j];
                FMA2(qa[2*j],   w.x, u[jj], qa[2*j]);
                FMA2(qa[2*j+1], w.y, u[jj], qa[2*j+1]);
            }
        }
    }

    // logits + softmax
    int lh = oy >> 1, lw = ox >> 1;
    float att[25];
    float mx = -1e30f;
#pragma unroll
    for (int o = 0; o < 25; o++) {
        int dy = o / 5, dx = o - 5 * dy;
        const ulonglong2* kp = (const ulonglong2*)&k_s[((lh + dy) * 12 + lw + dx) * KSTR];
        ull s0 = 0ull, s1 = 0ull;
#pragma unroll
        for (int j = 0; j < 8; j++) {
            ulonglong2 kv = kp[j];
            FMA2(s0, qa[2*j],   kv.x, s0);
            FMA2(s1, qa[2*j+1], kv.y, s1);
        }
        float p0, p1, p2, p3;
        unpack2(p0, p1, s0); unpack2(p2, p3, s1);
        float lg = (p0 + p1) + (p2 + p3);
        att[o] = lg;
        mx = fmaxf(mx, lg);
    }

    float den = 0.f;
#pragma unroll
    for (int o = 0; o < 25; o++) { float pz = __expf(att[o] - mx); att[o] = pz; den += pz; }
    float inv = 1.f / den;
#pragma unroll
    for (int o = 0; o < 25; o++)
        g_attn[((size_t)(b * 25 + o) << 14) + pixhi] = att[o] * inv;
}

// ============================================================
// Kernel 5: aggregation (R13 proven). grid (32, 4, 4) x 256.
// ============================================================
__global__ void __launch_bounds__(256)
agg_kernel(const float* __restrict__ x, float* __restrict__ out)
{
    __shared__ float x_s[240 * 12];

    int tid = threadIdx.x;
    int b   = blockIdx.z;
    int th0 = (blockIdx.x >> 2) * 8;
    int tw0 = (blockIdx.x & 3) * 16;
    int cb  = blockIdx.y * 64;

    int cp = tid & 15, r = tid >> 4;
    int gy2 = th0 * 2 + r, gx2 = tw0 * 2 + 2 * cp;
    int po  = (gy2 << 7) + gx2;
    int lh = r >> 1, lw = cp;

    float att0[25], att1[25];
#pragma unroll
    for (int o = 0; o < 25; o++) {
        float2 a = *(const float2*)&g_attn[((size_t)(b * 25 + o) << 14) + po];
        att0[o] = a.x; att1[o] = a.y;
    }

    const float* xb = x + (size_t)b * C_ * NPIX_LO;
    float* ob = out + (size_t)b * C_ * NPIX_HI + po;

    for (int cg = 0; cg < 8; cg++) {
        int c0 = cb + cg * 8;
        __syncthreads();
        for (int i = tid; i < 1920; i += 256) {
            int ch = i / 240, pt = i - ch * 240;
            int jy = pt / 20, jx = pt - jy * 20;
            int gy = th0 - 2 + jy, gx = tw0 - 2 + jx;
            float v = 0.f;
            if (gy >= 0 && gy < 64 && gx >= 0 && gx < 64)
                v = xb[(size_t)(c0 + ch) * NPIX_LO + (gy << 6) + gx];
            x_s[pt * 12 + ch] = v;
        }
        __syncthreads();

        ull a0[4], a1[4];
#pragma unroll
        for (int j = 0; j < 4; j++) { a0[j] = 0ull; a1[j] = 0ull; }
#pragma unroll
        for (int o = 0; o < 25; o++) {
            int dy = o / 5, dx = o - 5 * dy;
            const ulonglong2* xp = (const ulonglong2*)&x_s[((lh + dy) * 20 + lw + dx) * 12];
            ulonglong2 v0 = xp[0], v1 = xp[1];
            ull w0 = dup2(att0[o]), w1 = dup2(att1[o]);
            FMA2(a0[0], w0, v0.x, a0[0]); FMA2(a0[1], w0, v0.y, a0[1]);
            FMA2(a0[2], w0, v1.x, a0[2]); FMA2(a0[3], w0, v1.y, a0[3]);
            FMA2(a1[0], w1, v0.x, a1[0]); FMA2(a1[1], w1, v0.y, a1[1]);
            FMA2(a1[2], w1, v1.x, a1[2]); FMA2(a1[3], w1, v1.y, a1[3]);
        }
#pragma unroll
        for (int j = 0; j < 4; j++) {
            float l0, h0, l1, h1;
            unpack2(l0, h0, a0[j]);
            unpack2(l1, h1, a1[j]);
            *(ull*)&ob[(size_t)(c0 + 2*j)     * NPIX_HI] = pack2(l0, l1);
            *(ull*)&ob[(size_t)(c0 + 2*j + 1) * NPIX_HI] = pack2(h0, h1);
        }
    }
}

// ============================================================
extern "C" void kernel_launch(void* const* d_in, const int* in_sizes, int n_in,
                              void* d_out, int out_size)
{
    (void)in_sizes; (void)n_in; (void)out_size;
    const float* y      = (const float*)d_in[0];
    const float* x      = (const float*)d_in[1];
    const float* gn_y_w = (const float*)d_in[2];
    const float* gn_y_b = (const float*)d_in[3];
    const float* gn_x_w = (const float*)d_in[4];
    const float* gn_x_b = (const float*)d_in[5];
    const float* q_w    = (const float*)d_in[6];
    const float* q_b    = (const float*)d_in[7];
    const float* k_w    = (const float*)d_in[8];
    const float* k_b    = (const float*)d_in[9];
    float* out = (float*)d_out;

    stats_partial_kernel<<<640, 256>>>(y, x);
    finalize_kernel<<<33, 256>>>(q_w, k_w, gn_y_w, gn_y_b, gn_x_w, gn_x_b);
    kproj_kernel<<<dim3(NPIX_LO / 32, B_), 256>>>(x, k_b);

    static const size_t smemA = 14912 * sizeof(float);   // 59648 B
    cudaFuncSetAttribute(attn_kernel,
                         cudaFuncAttributeMaxDynamicSharedMemorySize, (int)smemA);
    attn_kernel<<<dim3(8, 8, 4), 256, smemA>>>(y, q_b);

    agg_kernel<<<dim3(32, 4, 4), 256>>>(x, out);
}

// round 17
// speedup vs baseline: 1.0531x; 1.0531x over previous
#include <cuda_runtime.h>
#include <cuda_bf16.h>
#include <cstddef>

// SAPA R17: R13 pipeline + resident-tile agg (single fill, no chunk barriers).
#define B_      4
#define C_      256
#define E_      32
#define NPIX_LO 4096
#define NPIX_HI 16384
#define EPSF    1e-5f
#define XSTR    68      // padded stride for agg x tile (16B-aligned, low-conflict)

typedef unsigned long long ull;

#define FMA2(d, a, b, c) \
    asm("fma.rn.f32x2 %0, %1, %2, %3;" : "=l"(d) : "l"(a), "l"(b), "l"(c))

__device__ __forceinline__ ull pack2(float lo, float hi) {
    ull r; asm("mov.b64 %0, {%1, %2};" : "=l"(r) : "f"(lo), "f"(hi)); return r;
}
__device__ __forceinline__ ull dup2(float v) { return pack2(v, v); }
__device__ __forceinline__ void unpack2(float& lo, float& hi, ull d) {
    asm("mov.b64 {%0, %1}, %2;" : "=f"(lo), "=f"(hi) : "l"(d));
}

// ---------------- device scratch ----------------
__device__ float  g_ps[640];
__device__ float  g_pss[640];
__device__ float2 g_st_y[B_ * C_];
__device__ float2 g_st_x[B_ * C_];
__device__ float  g_qwT[C_ * E_];                  // [c][e]
__device__ float  g_kwT[C_ * E_];                  // [c][e]
__device__ float  g_k[B_ * E_ * NPIX_LO];          // [b][e][pix_lo]
__device__ float  g_logits[2 * B_ * 25 * NPIX_HI]; // [half][b][o][pix_hi]
__device__ float  g_attn[B_ * 25 * NPIX_HI];       // [b][o][pix_hi]

// ============================================================
// Kernel 1: partial sums. blocks [0,512): y chunks; [512,640): x groups.
// ============================================================
__global__ void __launch_bounds__(256)
stats_partial_kernel(const float* __restrict__ y, const float* __restrict__ x)
{
    int bid = blockIdx.x, tid = threadIdx.x;
    const float4* p = (bid < 512)
        ? (const float4*)y + (size_t)bid * 8192
        : (const float4*)x + (size_t)(bid - 512) * 8192;

    float s = 0.f, ss = 0.f;
#pragma unroll 4
    for (int i = tid; i < 8192; i += 256) {
        float4 v = p[i];
        s  += (v.x + v.y) + (v.z + v.w);
        ss += (v.x*v.x + v.y*v.y) + (v.z*v.z + v.w*v.w);
    }
#pragma unroll
    for (int off = 16; off > 0; off >>= 1) {
        s  += __shfl_xor_sync(0xffffffffu, s,  off);
        ss += __shfl_xor_sync(0xffffffffu, ss, off);
    }
    __shared__ float ws[8], wss[8];
    if ((tid & 31) == 0) { ws[tid >> 5] = s; wss[tid >> 5] = ss; }
    __syncthreads();
    if (tid == 0) {
        float ts = 0.f, tss = 0.f;
#pragma unroll
        for (int w = 0; w < 8; w++) { ts += ws[w]; tss += wss[w]; }
        g_ps[bid] = ts; g_pss[bid] = tss;
    }
}

// ============================================================
// Kernel 2: finalize stats -> tables; transpose weights.
// ============================================================
__global__ void __launch_bounds__(256)
finalize_kernel(const float* __restrict__ qw, const float* __restrict__ kw,
                const float* __restrict__ gyw, const float* __restrict__ gyb,
                const float* __restrict__ gxw, const float* __restrict__ gxb)
{
    int tid = threadIdx.x;
    if (blockIdx.x == 0) {
        __shared__ float mu_s[256], rs_s[256];
        {
            float s, ss, n;
            if (tid < 128) {
                s  = (g_ps[4*tid]  + g_ps[4*tid+1])  + (g_ps[4*tid+2]  + g_ps[4*tid+3]);
                ss = (g_pss[4*tid] + g_pss[4*tid+1]) + (g_pss[4*tid+2] + g_pss[4*tid+3]);
                n = 131072.f;
            } else {
                int g = tid - 128;
                s = g_ps[512 + g]; ss = g_pss[512 + g]; n = 32768.f;
            }
            float mu  = s / n;
            float var = ss / n - mu * mu;
            mu_s[tid] = mu; rs_s[tid] = rsqrtf(var + EPSF);
        }
        __syncthreads();
        for (int i = tid; i < 1024; i += 256) {
            int b = i >> 8, c = i & 255, g = c >> 3;
            {
                float mu = mu_s[b*32 + g], r = rs_s[b*32 + g];
                float sc = r * gyw[c];
                g_st_y[i] = make_float2(sc, gyb[c] - mu * sc);
            }
            {
                float mu = mu_s[128 + b*32 + g], r = rs_s[128 + b*32 + g];
                float sc = r * gxw[c];
                g_st_x[i] = make_float2(sc, gxb[c] - mu * sc);
            }
        }
    } else {
        int i = (blockIdx.x - 1) * 256 + tid;
        int c = i >> 5, e = i & 31;
        g_qwT[i] = qw[e * C_ + c];
        g_kwT[i] = kw[e * C_ + c];
    }
}

// ============================================================
// Kernel 3: k projection (R7 exact). grid (128, 4) x 256.
// ============================================================
__global__ void __launch_bounds__(256)
kproj_kernel(const float* __restrict__ x, const float* __restrict__ k_b)
{
    __shared__ float sm[8448 + 512];
    float* w_s = sm;
    float* r_s = sm;
    float* s_s = sm + 8448;
    float* t_s = sm + 8704;

    int tid = threadIdx.x;
    int b   = blockIdx.y;
    int p   = tid & 31;
    int pix = blockIdx.x * 32 + p;

    for (int i = tid; i < (C_ * E_) / 4; i += 256)
        ((float4*)w_s)[i] = ((const float4*)g_kwT)[i];
    {
        float2 st = g_st_x[b * C_ + tid];
        s_s[tid] = st.x; t_s[tid] = st.y;
    }
    __syncthreads();

    const float* xp = x + (size_t)b * C_ * NPIX_LO + pix;
    const ulonglong2* w2 = (const ulonglong2*)w_s;
    const float4* s4 = (const float4*)s_s;
    const float4* t4 = (const float4*)t_s;

    ull qa2[16];
#pragma unroll
    for (int j = 0; j < 16; j++) qa2[j] = 0ull;

    int cbase = (tid >> 5) * 32;
#pragma unroll 2
    for (int c0 = cbase; c0 < cbase + 32; c0 += 8) {
        float xv[8];
#pragma unroll
        for (int j = 0; j < 8; j++)
            xv[j] = xp[(size_t)(c0 + j) * NPIX_LO];
        float4 scA = s4[c0 >> 2], tcA = t4[c0 >> 2];
        float4 scB = s4[(c0 >> 2) + 1], tcB = t4[(c0 >> 2) + 1];
        ull u[8];
        u[0] = dup2(fmaf(xv[0], scA.x, tcA.x));
        u[1] = dup2(fmaf(xv[1], scA.y, tcA.y));
        u[2] = dup2(fmaf(xv[2], scA.z, tcA.z));
        u[3] = dup2(fmaf(xv[3], scA.w, tcA.w));
        u[4] = dup2(fmaf(xv[4], scB.x, tcB.x));
        u[5] = dup2(fmaf(xv[5], scB.y, tcB.y));
        u[6] = dup2(fmaf(xv[6], scB.z, tcB.z));
        u[7] = dup2(fmaf(xv[7], scB.w, tcB.w));
#pragma unroll
        for (int jj = 0; jj < 8; jj++) {
#pragma unroll
            for (int j = 0; j < 8; j++) {
                ulonglong2 wv = w2[(c0 + jj) * 8 + j];
                FMA2(qa2[2*j],   wv.x, u[jj], qa2[2*j]);
                FMA2(qa2[2*j+1], wv.y, u[jj], qa2[2*j+1]);
            }
        }
    }

    __syncthreads();
#pragma unroll
    for (int j = 0; j < 16; j++) {
        float lo, hi; unpack2(lo, hi, qa2[j]);
        r_s[tid * 33 + 2*j]     = lo;
        r_s[tid * 33 + 2*j + 1] = hi;
    }
    __syncthreads();

    int q4 = tid >> 5;
    int p2 = tid & 31;
    float acc[4];
#pragma unroll
    for (int j = 0; j < 4; j++) acc[j] = __ldg(&k_b[q4 * 4 + j]);
#pragma unroll
    for (int s = 0; s < 8; s++) {
        const float* rp = &r_s[(s * 32 + p2) * 33 + q4 * 4];
#pragma unroll
        for (int j = 0; j < 4; j++) acc[j] += rp[j];
    }
    int pix2 = blockIdx.x * 32 + p2;
#pragma unroll
    for (int j = 0; j < 4; j++)
        g_k[((size_t)(b * E_ + q4 * 4 + j) << 12) + pix2] = acc[j];
}

// ============================================================
// Kernel 4: partial q-proj (c-half) + partial logits (R13 exact).
// grid (4,8,8) x 256.
// ============================================================
__global__ void __launch_bounds__(256, 2)
attn_partial_kernel(const float* __restrict__ y, const float* __restrict__ q_b)
{
    extern __shared__ float smA[];
    float* w_s  = smA;
    float* sy_s = smA + 4096;
    float* ty_s = smA + 4224;
    float* k_s  = smA + 4352;

    int tid  = threadIdx.x;
    int b    = blockIdx.z >> 1;
    int half = blockIdx.z & 1;
    int th0  = blockIdx.y * 8;
    int tw0  = blockIdx.x * 16;

    for (int i = tid; i < 1024; i += 256)
        ((float4*)w_s)[i] = ((const float4*)g_qwT)[half * 1024 + i];
    if (tid < 128) {
        float2 st = g_st_y[b * C_ + half * 128 + tid];
        sy_s[tid] = st.x; ty_s[tid] = st.y;
    }
    for (int i = tid; i < 7680; i += 256) {
        int e  = i / 240, pt = i - e * 240;
        int jy = pt / 20, jx = pt - jy * 20;
        int gy = th0 - 2 + jy, gx = tw0 - 2 + jx;
        float v = 0.f;
        if (gy >= 0 && gy < 64 && gx >= 0 && gx < 64)
            v = g_k[((size_t)(b * E_ + e) << 12) + (gy << 6) + gx];
        k_s[pt * 36 + e] = v;
    }
    __syncthreads();

    int cp = tid & 15, r = tid >> 4;
    int gy2 = th0 * 2 + r;
    int gx2 = tw0 * 2 + 2 * cp;
    const float* yp = y + ((size_t)b * C_ + half * 128) * NPIX_HI + (gy2 << 7) + gx2;
    const ulonglong2* w2 = (const ulonglong2*)w_s;
    const float4* sy4 = (const float4*)sy_s;
    const float4* ty4 = (const float4*)ty_s;

    ull a0[16], a1[16];
#pragma unroll
    for (int j = 0; j < 16; j++) {
        ull iv = half ? 0ull : pack2(__ldg(&q_b[2*j]), __ldg(&q_b[2*j + 1]));
        a0[j] = iv; a1[j] = iv;
    }

    float2 yv[4], yn[4];
#pragma unroll
    for (int j = 0; j < 4; j++)
        yv[j] = *(const float2*)(yp + (size_t)j * NPIX_HI);

    for (int c0 = 0; c0 < 128; c0 += 4) {
        if (c0 + 4 < 128) {
#pragma unroll
            for (int j = 0; j < 4; j++)
                yn[j] = *(const float2*)(yp + (size_t)(c0 + 4 + j) * NPIX_HI);
        }
        float4 sc = sy4[c0 >> 2], tc = ty4[c0 >> 2];
        ull u00 = dup2(fmaf(yv[0].x, sc.x, tc.x)), u01 = dup2(fmaf(yv[0].y, sc.x, tc.x));
        ull u10 = dup2(fmaf(yv[1].x, sc.y, tc.y)), u11 = dup2(fmaf(yv[1].y, sc.y, tc.y));
        ull u20 = dup2(fmaf(yv[2].x, sc.z, tc.z)), u21 = dup2(fmaf(yv[2].y, sc.z, tc.z));
        ull u30 = dup2(fmaf(yv[3].x, sc.w, tc.w)), u31 = dup2(fmaf(yv[3].y, sc.w, tc.w));
#pragma unroll
        for (int j = 0; j < 8; j++) {
            ulonglong2 w0 = w2[(c0 + 0) * 8 + j];
            FMA2(a0[2*j],   w0.x, u00, a0[2*j]);   FMA2(a0[2*j+1], w0.y, u00, a0[2*j+1]);
            FMA2(a1[2*j],   w0.x, u01, a1[2*j]);   FMA2(a1[2*j+1], w0.y, u01, a1[2*j+1]);
            ulonglong2 w1 = w2[(c0 + 1) * 8 + j];
            FMA2(a0[2*j],   w1.x, u10, a0[2*j]);   FMA2(a0[2*j+1], w1.y, u10, a0[2*j+1]);
            FMA2(a1[2*j],   w1.x, u11, a1[2*j]);   FMA2(a1[2*j+1], w1.y, u11, a1[2*j+1]);
            ulonglong2 wv = w2[(c0 + 2) * 8 + j];
            FMA2(a0[2*j],   wv.x, u20, a0[2*j]);   FMA2(a0[2*j+1], wv.y, u20, a0[2*j+1]);
            FMA2(a1[2*j],   wv.x, u21, a1[2*j]);   FMA2(a1[2*j+1], wv.y, u21, a1[2*j+1]);
            ulonglong2 w3 = w2[(c0 + 3) * 8 + j];
            FMA2(a0[2*j],   w3.x, u30, a0[2*j]);   FMA2(a0[2*j+1], w3.y, u30, a0[2*j+1]);
            FMA2(a1[2*j],   w3.x, u31, a1[2*j]);   FMA2(a1[2*j+1], w3.y, u31, a1[2*j+1]);
        }
#pragma unroll
        for (int j = 0; j < 4; j++) yv[j] = yn[j];
    }

    int lh = r >> 1, lw = cp;
    int pixhi = (gy2 << 7) + gx2;
    float* lg = g_logits + ((size_t)((half * B_ + b) * 25) << 14) + pixhi;
#pragma unroll
    for (int o = 0; o < 25; o++) {
        int dy = o / 5, dx = o - 5 * dy;
        const ulonglong2* kp = (const ulonglong2*)&k_s[((lh + dy) * 20 + lw + dx) * 36];
        ull s0 = 0ull, s1 = 0ull, t0 = 0ull, t1 = 0ull;
#pragma unroll
        for (int j = 0; j < 8; j++) {
            ulonglong2 kv = kp[j];
            FMA2(s0, a0[2*j],   kv.x, s0);  FMA2(s1, a0[2*j+1], kv.y, s1);
            FMA2(t0, a1[2*j],   kv.x, t0);  FMA2(t1, a1[2*j+1], kv.y, t1);
        }
        float p0,p1,p2,p3,q0,q1,q2,q3;
        unpack2(p0, p1, s0); unpack2(p2, p3, s1);
        unpack2(q0, q1, t0); unpack2(q2, q3, t1);
        *(float2*)&lg[(size_t)o << 14] =
            make_float2((p0 + p1) + (p2 + p3), (q0 + q1) + (q2 + q3));
    }
}

// ============================================================
// Kernel 5: sum halves + softmax -> g_attn.  grid 512 x 128.
// ============================================================
__global__ void __launch_bounds__(128)
softmax_kernel()
{
    int i = blockIdx.x * 128 + threadIdx.x;
    int b = i >> 14, pix = i & 16383;
    const float* l0 = g_logits + ((size_t)(b * 25) << 14) + pix;
    const float* l1 = g_logits + ((size_t)((B_ + b) * 25) << 14) + pix;

    float att[25];
    float mx = -1e30f;
#pragma unroll
    for (int o = 0; o < 25; o++) {
        float v = l0[(size_t)o << 14] + l1[(size_t)o << 14];
        att[o] = v;
        mx = fmaxf(mx, v);
    }
    float den = 0.f;
#pragma unroll
    for (int o = 0; o < 25; o++) { float p = __expf(att[o] - mx); att[o] = p; den += p; }
    float inv = 1.f / den;
    float* ap = g_attn + ((size_t)(b * 25) << 14) + pix;
#pragma unroll
    for (int o = 0; o < 25; o++) ap[(size_t)o << 14] = att[o] * inv;
}

// ============================================================
// Kernel 6: aggregation, resident 64-ch x tile, single fill.
// grid (32, 4, 4) x 256; dynamic smem 240*68*4 = 65280 B.
// Thread = 2 adjacent hi px; 8 chunks of 8 ch, no inner barriers.
// ============================================================
__global__ void __launch_bounds__(256)
agg_kernel(const float* __restrict__ x, float* __restrict__ out)
{
    extern __shared__ float x_s[];     // [pt][ch] stride XSTR

    int tid = threadIdx.x;
    int b   = blockIdx.z;
    int th0 = (blockIdx.x >> 2) * 8;
    int tw0 = (blockIdx.x & 3) * 16;
    int cb  = blockIdx.y * 64;

    const float* xb = x + (size_t)b * C_ * NPIX_LO;

    // ---- single fill: thread tid -> halo point tid (240 active) ----
    {
        int pt = tid;
        if (pt < 240) {
            int jy = pt / 20, jx = pt - jy * 20;
            int gy = th0 - 2 + jy, gx = tw0 - 2 + jx;
            bool inb = (gy >= 0 && gy < 64 && gx >= 0 && gx < 64);
            const float* src = xb + (size_t)cb * NPIX_LO + ((gy << 6) + gx);
            float* dst = &x_s[pt * XSTR];
            if (inb) {
#pragma unroll 8
                for (int ch = 0; ch < 64; ch++)
                    dst[ch] = src[(size_t)ch * NPIX_LO];
            } else {
#pragma unroll 8
                for (int ch = 0; ch < 64; ch++)
                    dst[ch] = 0.f;
            }
        }
    }

    int cp = tid & 15, r = tid >> 4;
    int gy2 = th0 * 2 + r, gx2 = tw0 * 2 + 2 * cp;
    int po  = (gy2 << 7) + gx2;
    int lh = r >> 1, lw = cp;

    float att0[25], att1[25];
#pragma unroll
    for (int o = 0; o < 25; o++) {
        float2 a = *(const float2*)&g_attn[((size_t)(b * 25 + o) << 14) + po];
        att0[o] = a.x; att1[o] = a.y;
    }
    __syncthreads();

    float* ob = out + (size_t)b * C_ * NPIX_HI + po;

#pragma unroll 2
    for (int cg = 0; cg < 8; cg++) {
        int c0 = cb + cg * 8;
        ull a0[4], a1[4];
#pragma unroll
        for (int j = 0; j < 4; j++) { a0[j] = 0ull; a1[j] = 0ull; }
#pragma unroll
        for (int o = 0; o < 25; o++) {
            int dy = o / 5, dx = o - 5 * dy;
            const ulonglong2* xp = (const ulonglong2*)
                &x_s[((lh + dy) * 20 + lw + dx) * XSTR + cg * 8];
            ulonglong2 v0 = xp[0], v1 = xp[1];
            ull w0 = dup2(att0[o]), w1 = dup2(att1[o]);
            FMA2(a0[0], w0, v0.x, a0[0]); FMA2(a0[1], w0, v0.y, a0[1]);
            FMA2(a0[2], w0, v1.x, a0[2]); FMA2(a0[3], w0, v1.y, a0[3]);
            FMA2(a1[0], w1, v0.x, a1[0]); FMA2(a1[1], w1, v0.y, a1[1]);
            FMA2(a1[2], w1, v1.x, a1[2]); FMA2(a1[3], w1, v1.y, a1[3]);
        }
#pragma unroll
        for (int j = 0; j < 4; j++) {
            float l0, h0, l1, h1;
            unpack2(l0, h0, a0[j]);
            unpack2(l1, h1, a1[j]);
            *(ull*)&ob[(size_t)(c0 + 2*j)     * NPIX_HI] = pack2(l0, l1);
            *(ull*)&ob[(size_t)(c0 + 2*j + 1) * NPIX_HI] = pack2(h0, h1);
        }
    }
}

// ============================================================
extern "C" void kernel_launch(void* const* d_in, const int* in_sizes, int n_in,
                              void* d_out, int out_size)
{
    (void)in_sizes; (void)n_in; (void)out_size;
    const float* y      = (const float*)d_in[0];
    const float* x      = (const float*)d_in[1];
    const float* gn_y_w = (const float*)d_in[2];
    const float* gn_y_b = (const float*)d_in[3];
    const float* gn_x_w = (const float*)d_in[4];
    const float* gn_x_b = (const float*)d_in[5];
    const float* q_w    = (const float*)d_in[6];
    const float* q_b    = (const float*)d_in[7];
    const float* k_w    = (const float*)d_in[8];
    const float* k_b    = (const float*)d_in[9];
    float* out = (float*)d_out;

    stats_partial_kernel<<<640, 256>>>(y, x);
    finalize_kernel<<<33, 256>>>(q_w, k_w, gn_y_w, gn_y_b, gn_x_w, gn_x_b);
    kproj_kernel<<<dim3(NPIX_LO / 32, B_), 256>>>(x, k_b);

    static const size_t smemA = (4096 + 128 + 128 + 240 * 36) * sizeof(float); // 51968
    cudaFuncSetAttribute(attn_partial_kernel,
                         cudaFuncAttributeMaxDynamicSharedMemorySize, (int)smemA);
    attn_partial_kernel<<<dim3(4, 8, 2 * B_), 256, smemA>>>(y, q_b);

    softmax_kernel<<<512, 128>>>();

    static const size_t smemG = 240 * XSTR * sizeof(float);   // 65280
    cudaFuncSetAttribute(agg_kernel,
                         cudaFuncAttributeMaxDynamicSharedMemorySize, (int)smemG);
    agg_kernel<<<dim3(32, 4, 4), 256, smemG>>>(x, out);
}